// round 1
// baseline (speedup 1.0000x reference)
#include <cuda_runtime.h>

// ---------------------------------------------------------------------------
// pairs_of_pairs: fused feature-build + 3x (1x1 conv 256->256 + bias + ReLU)
//
// Geometry (hardcoded from reference):
//   B=32, C=64, S=64, CC=128, OC=256, J=S-1=63
//   input vector per pixel (b,j,i), 256 channels:
//     [0:128)   xc[b, :, j, i]
//     [128:192) x[b, :, i]
//     [192:256) x[b, :, (i - (j+1)) mod 64]
//   out[b, o, j, i] = relu(W3 @ relu(W2 @ relu(W1 @ v + b1) + b2) + b3)
//
// Strategy: one CTA per (b, j): 64 pixels. Full 256-ch activation tile lives
// in smem (ping-pong buffers). Weights streamed from L2 in K-chunks of 16
// with register prefetch (transposed to [k][o] in smem so W reads vectorize
// and broadcast). 512 threads; each thread owns an 8(outch) x 4(px) register
// tile -> 32 FFMA per 3 LDS.128 per k-step (W LDS are broadcast => ~free).
// Layer 3 epilogue writes straight to global (coalesced float4).
// ---------------------------------------------------------------------------

namespace pp {
constexpr int S      = 64;
constexpr int JROWS  = 63;
constexpr int BATCH  = 32;
constexpr int CIN    = 256;
constexpr int OCH    = 256;
constexpr int KC     = 16;              // k-chunk staged in smem
constexpr int NCHUNK = CIN / KC;        // 16
constexpr int THREADS = 512;
// dynamic smem: Xa[256][64] | Xb[256][64] | Wb[16][256]
constexpr int SMEM_FLOATS = 2 * CIN * S + KC * OCH;   // 36864
constexpr int SMEM_BYTES  = SMEM_FLOATS * 4;          // 147456 (144 KB)
}
using namespace pp;

__device__ __forceinline__ void layer_gemm(
    const float* __restrict__ Wg,   // [OCH][CIN] row-major (global)
    const float* __restrict__ bg,   // [OCH] (global)
    const float* __restrict__ Xin,  // smem [CIN][S]
    float*       Xout,              // smem [OCH][S] (nullptr if writing global)
    float*       Wb,                // smem [KC][OCH]
    float*       gout,              // global base for this (b, j), or nullptr
    int tx, int ty, int tid)
{
    float acc[8][4];
#pragma unroll
    for (int a = 0; a < 8; ++a)
#pragma unroll
        for (int c = 0; c < 4; ++c) acc[a][c] = 0.f;

    // Weight staging: thread pair (o = tid>>1, half = tid&1) loads 8 contiguous
    // floats of row o per chunk, stores transposed into Wb[k][o].
    const int o    = tid >> 1;
    const int half = tid & 1;
    const float* wsrc = Wg + (size_t)o * CIN + half * 8;
    float4 p0 = *(const float4*)(wsrc);
    float4 p1 = *(const float4*)(wsrc + 4);

    const float* xbase = Xin + tx * 4;
    const float* wrow  = Wb + ty * 8;
    float*       wdst  = Wb + (half * 8) * OCH + o;

    for (int ch = 0; ch < NCHUNK; ++ch) {
        __syncthreads();                       // previous chunk fully consumed
        wdst[0 * OCH] = p0.x; wdst[1 * OCH] = p0.y;
        wdst[2 * OCH] = p0.z; wdst[3 * OCH] = p0.w;
        wdst[4 * OCH] = p1.x; wdst[5 * OCH] = p1.y;
        wdst[6 * OCH] = p1.z; wdst[7 * OCH] = p1.w;
        __syncthreads();                       // Wb ready
        if (ch + 1 < NCHUNK) {                 // prefetch next chunk (hidden by math)
            const float* nsrc = wsrc + (ch + 1) * KC;
            p0 = *(const float4*)(nsrc);
            p1 = *(const float4*)(nsrc + 4);
        }
        const float* xk = xbase + ch * KC * S;
#pragma unroll
        for (int k = 0; k < KC; ++k) {
            const float4 xv = *(const float4*)(xk + k * S);
            const float4 w0 = *(const float4*)(wrow + k * OCH);
            const float4 w1 = *(const float4*)(wrow + k * OCH + 4);
            const float xs[4] = {xv.x, xv.y, xv.z, xv.w};
            const float ws[8] = {w0.x, w0.y, w0.z, w0.w, w1.x, w1.y, w1.z, w1.w};
#pragma unroll
            for (int oo = 0; oo < 8; ++oo)
#pragma unroll
                for (int c = 0; c < 4; ++c)
                    acc[oo][c] += ws[oo] * xs[c];
        }
    }

    // epilogue: bias + relu, write smem (layers 1,2) or global (layer 3)
#pragma unroll
    for (int oo = 0; oo < 8; ++oo) {
        const float bv = __ldg(bg + ty * 8 + oo);
        float4 r;
        r.x = fmaxf(acc[oo][0] + bv, 0.f);
        r.y = fmaxf(acc[oo][1] + bv, 0.f);
        r.z = fmaxf(acc[oo][2] + bv, 0.f);
        r.w = fmaxf(acc[oo][3] + bv, 0.f);
        if (gout) {
            // out[., o, j, i]: o-stride = JROWS*S
            *(float4*)(gout + (size_t)(ty * 8 + oo) * (JROWS * S) + tx * 4) = r;
        } else {
            *(float4*)(Xout + (ty * 8 + oo) * S + tx * 4) = r;
        }
    }
}

__global__ __launch_bounds__(THREADS, 1)
void pairs3_kernel(const float* __restrict__ x,  const float* __restrict__ xc,
                   const float* __restrict__ W1, const float* __restrict__ b1,
                   const float* __restrict__ W2, const float* __restrict__ b2,
                   const float* __restrict__ W3, const float* __restrict__ b3,
                   float* __restrict__ out)
{
    extern __shared__ float smem[];
    float* Xa = smem;                 // [256][64]
    float* Xb = smem + CIN * S;       // [256][64]
    float* Wb = smem + 2 * CIN * S;   // [16][256]

    const int tid = threadIdx.x;
    const int b   = blockIdx.x / JROWS;
    const int j   = blockIdx.x % JROWS;

    // ---- build input tile ----
    // rows [0,128): xc[b, c, j, :]   rows [128,192): x[b, c, :]
    for (int r4 = tid; r4 < 192 * (S / 4); r4 += THREADS) {
        const int row = r4 >> 4;              // S/4 == 16
        const int col = (r4 & 15) * 4;
        const float* src = (row < 128)
            ? xc + (((size_t)b * 128 + row) * JROWS + j) * S + col
            : x  + ((size_t)b * 64 + (row - 128)) * S + col;
        *(float4*)&Xa[row * S + col] = *(const float4*)src;
    }
    __syncthreads();
    // rows [192,256): rolled = x row rotated by (j+1)
    {
        const int shift = j + 1;
        for (int idx = tid; idx < 64 * S; idx += THREADS) {
            const int c = idx >> 6;
            const int i = idx & 63;
            Xa[(192 + c) * S + i] = Xa[(128 + c) * S + ((i - shift) & (S - 1))];
        }
        // visibility guaranteed by layer_gemm's first two __syncthreads
        // (compute only starts after the second barrier)
    }

    const int tx = tid & 15;   // pixel group: i = tx*4 .. tx*4+3
    const int ty = tid >> 4;   // outch group: o = ty*8 .. ty*8+7

    layer_gemm(W1, b1, Xa, Xb, Wb, nullptr, tx, ty, tid);
    layer_gemm(W2, b2, Xb, Xa, Wb, nullptr, tx, ty, tid);
    float* gout = out + ((size_t)b * OCH * JROWS + j) * S;
    layer_gemm(W3, b3, Xa, nullptr, Wb, gout, tx, ty, tid);
}

extern "C" void kernel_launch(void* const* d_in, const int* in_sizes, int n_in,
                              void* d_out, int out_size)
{
    (void)in_sizes; (void)n_in; (void)out_size;
    const float* x  = (const float*)d_in[0];
    const float* xc = (const float*)d_in[1];
    const float* W1 = (const float*)d_in[2];
    const float* b1 = (const float*)d_in[3];
    const float* W2 = (const float*)d_in[4];
    const float* b2 = (const float*)d_in[5];
    const float* W3 = (const float*)d_in[6];
    const float* b3 = (const float*)d_in[7];
    float* out = (float*)d_out;

    cudaFuncSetAttribute(pairs3_kernel,
                         cudaFuncAttributeMaxDynamicSharedMemorySize, SMEM_BYTES);
    pairs3_kernel<<<BATCH * JROWS, THREADS, SMEM_BYTES>>>(
        x, xc, W1, b1, W2, b2, W3, b3, out);
}

// round 3
// speedup vs baseline: 2.0605x; 2.0605x over previous
#include <cuda_runtime.h>
#include <cuda_bf16.h>
#include <cstdint>

// ===========================================================================
// pairs_of_pairs — fused 3x (1x1 conv 256->256 + bias + ReLU), mma.sync bf16.
//
// NOTE: harness compiles PTX for base sm_100 (no 'a') -> tcgen05 unavailable.
// Tensor path here is the legacy warp-level mma.sync.m16n8k16 (HMMA), which
// IS supported, plus ldmatrix + cp.async.
//
// Math:  out = relu(W3 relu(W2 relu(W1 v + b1) + b2) + b3),  v per pixel:
//   [xc(128) | x(64) | rolled x(64)],  pixels px = j*64+i, PIX=4032 per batch.
// Precision: split W = Wh+Wl, X = Xh+Xl (bf16);  W·X ~= Wh·Xh + Wl·Xh + Wh·Xl
// (lo·lo dropped, ~1.5e-5 rel), fp32 accumulation.
//
// CTA: 128 pixels x 256 outch x K=256.  512 threads, warp grid 2(M) x 8(N),
// warp tile M64 x N32.  A (Xh, Xl) resident in smem, 528B padded rows
// (conflict-free ldmatrix).  W streamed in K=32 chunks, hi+lo, double
// buffered with cp.async.  Epilogue rewrites A in place for the next layer.
// ===========================================================================

namespace pp {
constexpr int BATCH = 32;
constexpr int PIX   = 63 * 64;        // 4032
constexpr int NT    = 128;            // pixels per CTA
constexpr int TILES = 32;             // 32*128 >= 4032 (last tile overlaps)
constexpr int THREADS = 512;
constexpr int KCH   = 32;             // weight k-chunk
constexpr int NCHUNK = 256 / KCH;     // 8

// A: [128 px][256 ch] bf16, row stride 528B (33 x 16B chunks -> bank-clean)
constexpr int A_STRIDE = 528;
constexpr int SM_AH = 0;
constexpr int SM_AL = 128 * A_STRIDE;            // 67584
// W: [256 n][32 k] bf16 per chunk, row stride 80B (5 x 16B). hi+lo per buf.
constexpr int W_STRIDE = 80;
constexpr int W_HALF   = 256 * W_STRIDE;         // 20480
constexpr int W_BUF    = 2 * W_HALF;             // 40960 (hi, lo)
constexpr int SM_W     = 2 * 128 * A_STRIDE;     // 135168
constexpr int SMEM_BYTES = SM_W + 2 * W_BUF;     // 217088
}
using namespace pp;

// pre-split weights: [layer][outch 256][k 256] bf16
__device__ __nv_bfloat16 g_Wh[3 * 256 * 256];
__device__ __nv_bfloat16 g_Wl[3 * 256 * 256];

__global__ void prep_split(const float* __restrict__ W1,
                           const float* __restrict__ W2,
                           const float* __restrict__ W3)
{
    int i = blockIdx.x * blockDim.x + threadIdx.x;   // [0, 65536)
    const float* Ws[3] = {W1, W2, W3};
#pragma unroll
    for (int l = 0; l < 3; ++l) {
        float v = Ws[l][i];
        __nv_bfloat16 h = __float2bfloat16(v);
        g_Wh[l * 65536 + i] = h;
        g_Wl[l * 65536 + i] = __float2bfloat16(v - __bfloat162float(h));
    }
}

// ------------------------------ device asm ---------------------------------
__device__ __forceinline__ uint32_t smem_u32(const void* p) {
    uint32_t a;
    asm("{ .reg .u64 t; cvta.to.shared.u64 t, %1; cvt.u32.u64 %0, t; }"
        : "=r"(a) : "l"(p));
    return a;
}
__device__ __forceinline__ void ldsm4(uint32_t r[4], uint32_t addr) {
    asm volatile("ldmatrix.sync.aligned.m8n8.x4.shared.b16 {%0,%1,%2,%3}, [%4];"
                 : "=r"(r[0]), "=r"(r[1]), "=r"(r[2]), "=r"(r[3]) : "r"(addr));
}
__device__ __forceinline__ void mma16816(float d[4], const uint32_t a[4],
                                         uint32_t b0, uint32_t b1) {
    asm volatile(
        "mma.sync.aligned.m16n8k16.row.col.f32.bf16.bf16.f32 "
        "{%0,%1,%2,%3}, {%4,%5,%6,%7}, {%8,%9}, {%0,%1,%2,%3};"
        : "+f"(d[0]), "+f"(d[1]), "+f"(d[2]), "+f"(d[3])
        : "r"(a[0]), "r"(a[1]), "r"(a[2]), "r"(a[3]), "r"(b0), "r"(b1));
}
__device__ __forceinline__ void cp16(uint32_t s, const void* g) {
    asm volatile("cp.async.cg.shared.global [%0], [%1], 16;" :: "r"(s), "l"(g));
}
#define CP_COMMIT() asm volatile("cp.async.commit_group;" ::: "memory")
#define CP_WAIT0()  asm volatile("cp.async.wait_group 0;"  ::: "memory")

__device__ __forceinline__ uint32_t pack_bf16x2(float lo, float hi) {
    return ((uint32_t)__bfloat16_as_ushort(__float2bfloat16(hi)) << 16) |
           (uint32_t)__bfloat16_as_ushort(__float2bfloat16(lo));
}

// ------------------------------- main kernel -------------------------------
__global__ __launch_bounds__(THREADS, 1)
void pairs_mma_kernel(const float* __restrict__ x,
                      const float* __restrict__ xc,
                      const float* __restrict__ b1,
                      const float* __restrict__ b2,
                      const float* __restrict__ b3,
                      float* __restrict__ out)
{
    extern __shared__ char smem[];
    const uint32_t sb = smem_u32(smem);
    const int tid  = threadIdx.x;
    const int lane = tid & 31;
    const int warp = tid >> 5;

    const int b = blockIdx.x / TILES;
    const int t = blockIdx.x % TILES;
    int px_base = t * NT;
    if (px_base > PIX - NT) px_base = PIX - NT;      // 3904, multiple of 64
    const int j0 = px_base >> 6;

    // ---------------- build A (Xh, Xl) in smem ----------------
    // fp32 staging [128 ch][128 px] overlays the W buffers (used before them)
    float* Xs = (float*)(smem + SM_W);
    for (int pass = 0; pass < 2; ++pass) {
        __syncthreads();
        if (pass == 0) {
            const float* src = xc + (size_t)b * 128 * PIX + px_base;
            for (int u = tid; u < 128 * 32; u += THREADS) {
                int row = u >> 5, c4 = (u & 31) << 2;
                *(float4*)&Xs[row * 128 + c4] =
                    *(const float4*)(src + (size_t)row * PIX + c4);
            }
        } else {
            const float* xr = x + (size_t)b * 64 * 64;
            for (int u = tid; u < 128 * 128; u += THREADS) {
                int row = u >> 7, col = u & 127;
                int c2 = row & 63, s = col >> 6, i = col & 63;
                Xs[row * 128 + col] = (row < 64)
                    ? xr[c2 * 64 + i]
                    : xr[c2 * 64 + ((i - (j0 + s + 1)) & 63)];
            }
        }
        __syncthreads();
        // convert 32 channels per thread-group into A[px][ch]
        const int px = tid & 127;
        const int grp = tid >> 7;             // 0..3
        const int ch_lo = grp * 32;
#pragma unroll
        for (int kk = 0; kk < 16; ++kk) {
            int c = ch_lo + 2 * kk;
            float a = Xs[c * 128 + px];
            float cgv = Xs[(c + 1) * 128 + px];
            float ah = __bfloat162float(__float2bfloat16(a));
            float ch2 = __bfloat162float(__float2bfloat16(cgv));
            int chn = pass * 128 + c;
            uint32_t off = (uint32_t)(px * A_STRIDE + ((chn >> 3) << 4) + ((chn & 7) << 1));
            *(uint32_t*)(smem + SM_AH + off) = pack_bf16x2(a, cgv);
            *(uint32_t*)(smem + SM_AL + off) = pack_bf16x2(a - ah, cgv - ch2);
        }
    }
    __syncthreads();

    // ---------------- warp tiling ----------------
    const int warp_m = warp & 1;              // 0..1  -> m0 = warp_m*64
    const int warp_n = warp >> 1;             // 0..7  -> n0 = warp_n*32
    const int m0 = warp_m * 64;
    const int n0 = warp_n * 32;

    // per-lane ldmatrix address components
    const uint32_t a_lane = (uint32_t)((lane & 15) * A_STRIDE + ((lane >> 4) << 4));
    const uint32_t w_lane = (uint32_t)((lane & 15) * W_STRIDE + ((lane >> 4) << 4));
    const uint32_t ah_base = sb + SM_AH + (uint32_t)(m0 * A_STRIDE) + a_lane;
    const uint32_t al_base = sb + SM_AL + (uint32_t)(m0 * A_STRIDE) + a_lane;

    const int qrow = lane >> 2;               // 0..7
    const int qcol = (lane & 3) * 2;          // 0,2,4,6

    float* ob = out + (size_t)b * 256 * PIX + px_base;

    for (int L = 0; L < 3; ++L) {
        float acc[4][4][4];
#pragma unroll
        for (int mt = 0; mt < 4; ++mt)
#pragma unroll
            for (int nt = 0; nt < 4; ++nt)
#pragma unroll
                for (int q = 0; q < 4; ++q) acc[mt][nt][q] = 0.f;

        const __nv_bfloat16* WhL = g_Wh + (size_t)L * 65536;
        const __nv_bfloat16* WlL = g_Wl + (size_t)L * 65536;

        // prefetch chunk 0 into buf 0
        {
            for (int it = 0; it < 4; ++it) {
                int u = tid + it * THREADS;           // [0,2048)
                int sel = u >> 10, v = u & 1023;
                int row = v >> 2, seg = v & 3;
                const __nv_bfloat16* gsrc =
                    (sel ? WlL : WhL) + row * 256 + /*c=0*/ seg * 8;
                cp16(sb + SM_W + (uint32_t)(sel * W_HALF + row * W_STRIDE + seg * 16), gsrc);
            }
            CP_COMMIT();
        }

        for (int c = 0; c < NCHUNK; ++c) {
            CP_WAIT0();
            __syncthreads();      // chunk c visible; all warps past chunk c-1
            if (c + 1 < NCHUNK) {
                uint32_t dbuf = sb + SM_W + (uint32_t)(((c + 1) & 1) * W_BUF);
                for (int it = 0; it < 4; ++it) {
                    int u = tid + it * THREADS;
                    int sel = u >> 10, v = u & 1023;
                    int row = v >> 2, seg = v & 3;
                    const __nv_bfloat16* gsrc =
                        (sel ? WlL : WhL) + row * 256 + (c + 1) * KCH + seg * 8;
                    cp16(dbuf + (uint32_t)(sel * W_HALF + row * W_STRIDE + seg * 16), gsrc);
                }
                CP_COMMIT();
            }

            const uint32_t wb = sb + SM_W + (uint32_t)((c & 1) * W_BUF);
            const uint32_t wh_base = wb + (uint32_t)(n0 * W_STRIDE) + w_lane;
            const uint32_t wl_base = wh_base + W_HALF;

#pragma unroll
            for (int ks = 0; ks < 2; ++ks) {
                const int kg = c * KCH + ks * 16;
                uint32_t afr[4][4], bh[2][4], bl[2][4];
#pragma unroll
                for (int mt = 0; mt < 4; ++mt)
                    ldsm4(afr[mt], ah_base + (uint32_t)(mt * 16 * A_STRIDE + kg * 2));
#pragma unroll
                for (int n2 = 0; n2 < 2; ++n2) {
                    ldsm4(bh[n2], wh_base + (uint32_t)(n2 * 16 * W_STRIDE + ks * 32));
                    ldsm4(bl[n2], wl_base + (uint32_t)(n2 * 16 * W_STRIDE + ks * 32));
                }
                // Ah*Bh and Ah*Bl
#pragma unroll
                for (int mt = 0; mt < 4; ++mt)
#pragma unroll
                    for (int nt = 0; nt < 4; ++nt) {
                        const int n2 = nt >> 1, h = nt & 1;
                        mma16816(acc[mt][nt], afr[mt], bh[n2][h], bh[n2][h + 2]);
                        mma16816(acc[mt][nt], afr[mt], bl[n2][h], bl[n2][h + 2]);
                    }
                // reload A with lo, Al*Bh
#pragma unroll
                for (int mt = 0; mt < 4; ++mt)
                    ldsm4(afr[mt], al_base + (uint32_t)(mt * 16 * A_STRIDE + kg * 2));
#pragma unroll
                for (int mt = 0; mt < 4; ++mt)
#pragma unroll
                    for (int nt = 0; nt < 4; ++nt) {
                        const int n2 = nt >> 1, h = nt & 1;
                        mma16816(acc[mt][nt], afr[mt], bh[n2][h], bh[n2][h + 2]);
                    }
            }
        }

        __syncthreads();          // all reads of A done before rewrite

        const float* bl_ptr = (L == 0) ? b1 : (L == 1) ? b2 : b3;
        if (L < 2) {
#pragma unroll
            for (int mt = 0; mt < 4; ++mt) {
                const int pxr0 = m0 + mt * 16 + qrow;
#pragma unroll
                for (int nt = 0; nt < 4; ++nt) {
                    const int ch = n0 + nt * 8 + qcol;
                    const float bv0 = __ldg(bl_ptr + ch);
                    const float bv1 = __ldg(bl_ptr + ch + 1);
                    const uint32_t coff = (uint32_t)(((ch >> 3) << 4) + ((ch & 7) << 1));
#pragma unroll
                    for (int half = 0; half < 2; ++half) {
                        const int pxr = pxr0 + half * 8;
                        float v0 = fmaxf(acc[mt][nt][half * 2 + 0] + bv0, 0.f);
                        float v1 = fmaxf(acc[mt][nt][half * 2 + 1] + bv1, 0.f);
                        float h0 = __bfloat162float(__float2bfloat16(v0));
                        float h1 = __bfloat162float(__float2bfloat16(v1));
                        const uint32_t off = (uint32_t)(pxr * A_STRIDE) + coff;
                        *(uint32_t*)(smem + SM_AH + off) = pack_bf16x2(v0, v1);
                        *(uint32_t*)(smem + SM_AL + off) = pack_bf16x2(v0 - h0, v1 - h1);
                    }
                }
            }
            __syncthreads();      // new A visible before next layer
        } else {
#pragma unroll
            for (int mt = 0; mt < 4; ++mt) {
                const int pxr0 = m0 + mt * 16 + qrow;
#pragma unroll
                for (int nt = 0; nt < 4; ++nt) {
                    const int ch = n0 + nt * 8 + qcol;
                    const float bv0 = __ldg(bl_ptr + ch);
                    const float bv1 = __ldg(bl_ptr + ch + 1);
#pragma unroll
                    for (int half = 0; half < 2; ++half) {
                        const int pxr = pxr0 + half * 8;
                        ob[(size_t)ch * PIX + pxr] =
                            fmaxf(acc[mt][nt][half * 2 + 0] + bv0, 0.f);
                        ob[(size_t)(ch + 1) * PIX + pxr] =
                            fmaxf(acc[mt][nt][half * 2 + 1] + bv1, 0.f);
                    }
                }
            }
        }
    }
}

extern "C" void kernel_launch(void* const* d_in, const int* in_sizes, int n_in,
                              void* d_out, int out_size)
{
    (void)in_sizes; (void)n_in; (void)out_size;
    const float* x  = (const float*)d_in[0];
    const float* xc = (const float*)d_in[1];
    const float* W1 = (const float*)d_in[2];
    const float* b1 = (const float*)d_in[3];
    const float* W2 = (const float*)d_in[4];
    const float* b2 = (const float*)d_in[5];
    const float* W3 = (const float*)d_in[6];
    const float* b3 = (const float*)d_in[7];
    float* out = (float*)d_out;

    prep_split<<<256, 256>>>(W1, W2, W3);

    cudaFuncSetAttribute(pairs_mma_kernel,
                         cudaFuncAttributeMaxDynamicSharedMemorySize, SMEM_BYTES);
    pairs_mma_kernel<<<BATCH * TILES, THREADS, SMEM_BYTES>>>(
        x, xc, b1, b2, b3, out);
}

// round 5
// speedup vs baseline: 2.9336x; 1.4238x over previous
#include <cuda_runtime.h>
#include <cuda_fp16.h>
#include <cstdint>

// ===========================================================================
// pairs_of_pairs — fused 3x (1x1 conv 256->256 + bias + ReLU), mma.sync fp16.
//
// Precision scheme (R4): W = Wh + Wl (fp16 pair, 22-bit weights), X rounded
// once to fp16.  W·X ≈ Wh·Xh + Wl·Xh   (2 MMA terms; error ~= fp16 u = 4.9e-4
// per layer from X truncation only; ~3-5e-4 over 3 layers, gate is 1e-3).
// fp32 accumulation throughout; bias+ReLU in fp32.
//
// CTA: 128 pixels x 256 outch x K=256, 512 threads, warp grid 2(M) x 8(N),
// warp tile M64 x N32 (64 fp32 acc/thread).  A (Xh) resident in smem,
// 528B-padded rows (conflict-free ldmatrix).  W streamed in K=64 chunks
// (hi+lo, 144B-padded rows), double-buffered cp.async; next layer's first
// chunk prefetched under the epilogue.  MMA ordering: 16 independent hi
// then 16 independent lo (acc reuse distance = 16).
// ===========================================================================

namespace pp {
constexpr int BATCH = 32;
constexpr int PIX   = 63 * 64;        // 4032
constexpr int NT    = 128;            // pixels per CTA
constexpr int TILES = 32;             // 32*128 >= 4032 (last tile overlaps)
constexpr int THREADS = 512;
constexpr int KCH   = 64;             // weight k-chunk
constexpr int NCHUNK = 256 / KCH;     // 4

// A: [128 px][256 ch] fp16, row stride 528B (33 x 16B -> bank-clean ldsm)
constexpr int A_STRIDE = 528;
constexpr int SM_A     = 0;
constexpr int A_BYTES  = 128 * A_STRIDE;         // 67584
// W chunk: [256 n][64 k] fp16, row stride 144B (9 x 16B -> bank-clean).
constexpr int W_STRIDE = 144;
constexpr int W_HALF   = 256 * W_STRIDE;         // 36864 (one of hi/lo)
constexpr int W_BUF    = 2 * W_HALF;             // 73728
constexpr int SM_W     = A_BYTES;                // 67584
constexpr int SMEM_BYTES = SM_W + 2 * W_BUF;     // 215040
}
using namespace pp;

// pre-split weights: [layer][outch 256][k 256] fp16 (hi, lo)
__device__ __half g_Wh[3 * 256 * 256];
__device__ __half g_Wl[3 * 256 * 256];

__global__ void prep_split(const float* __restrict__ W1,
                           const float* __restrict__ W2,
                           const float* __restrict__ W3)
{
    int i = blockIdx.x * blockDim.x + threadIdx.x;   // [0, 65536)
    const float* Ws[3] = {W1, W2, W3};
#pragma unroll
    for (int l = 0; l < 3; ++l) {
        float v = Ws[l][i];
        __half h = __float2half_rn(v);
        g_Wh[l * 65536 + i] = h;
        g_Wl[l * 65536 + i] = __float2half_rn(v - __half2float(h));
    }
}

// ------------------------------ device asm ---------------------------------
__device__ __forceinline__ uint32_t smem_u32(const void* p) {
    uint32_t a;
    asm("{ .reg .u64 t; cvta.to.shared.u64 t, %1; cvt.u32.u64 %0, t; }"
        : "=r"(a) : "l"(p));
    return a;
}
__device__ __forceinline__ void ldsm4(uint32_t r[4], uint32_t addr) {
    asm volatile("ldmatrix.sync.aligned.m8n8.x4.shared.b16 {%0,%1,%2,%3}, [%4];"
                 : "=r"(r[0]), "=r"(r[1]), "=r"(r[2]), "=r"(r[3]) : "r"(addr));
}
__device__ __forceinline__ void mma16816(float d[4], const uint32_t a[4],
                                         uint32_t b0, uint32_t b1) {
    asm volatile(
        "mma.sync.aligned.m16n8k16.row.col.f32.f16.f16.f32 "
        "{%0,%1,%2,%3}, {%4,%5,%6,%7}, {%8,%9}, {%0,%1,%2,%3};"
        : "+f"(d[0]), "+f"(d[1]), "+f"(d[2]), "+f"(d[3])
        : "r"(a[0]), "r"(a[1]), "r"(a[2]), "r"(a[3]), "r"(b0), "r"(b1));
}
__device__ __forceinline__ void cp16(uint32_t s, const void* g) {
    asm volatile("cp.async.cg.shared.global [%0], [%1], 16;" :: "r"(s), "l"(g));
}
#define CP_COMMIT() asm volatile("cp.async.commit_group;" ::: "memory")
#define CP_WAIT0()  asm volatile("cp.async.wait_group 0;"  ::: "memory")

__device__ __forceinline__ uint32_t pack_h2(float lo, float hi) {
    return ((uint32_t)__half_as_ushort(__float2half_rn(hi)) << 16) |
           (uint32_t)__half_as_ushort(__float2half_rn(lo));
}

// weight-chunk loader: chunk c of layer ptrs into buffer at dbuf
__device__ __forceinline__ void load_wchunk(uint32_t dbuf,
                                            const __half* WhL,
                                            const __half* WlL,
                                            int c, int tid)
{
    // 256 rows x 8 segs x 16B per half; 4096 cp16 over 512 threads = 8 each
#pragma unroll
    for (int it = 0; it < 8; ++it) {
        int u = tid + it * THREADS;            // [0, 4096)
        int sel = u >> 11;                     // 0: hi, 1: lo
        int v = u & 2047;
        int row = v >> 3, seg = v & 7;
        const __half* gsrc = (sel ? WlL : WhL) + row * 256 + c * KCH + seg * 8;
        cp16(dbuf + (uint32_t)(sel * W_HALF + row * W_STRIDE + seg * 16), gsrc);
    }
    CP_COMMIT();
}

// ------------------------------- main kernel -------------------------------
__global__ __launch_bounds__(THREADS, 1)
void pairs_mma_kernel(const float* __restrict__ x,
                      const float* __restrict__ xc,
                      const float* __restrict__ b1,
                      const float* __restrict__ b2,
                      const float* __restrict__ b3,
                      float* __restrict__ out)
{
    extern __shared__ char smem[];
    const uint32_t sb = smem_u32(smem);
    const int tid  = threadIdx.x;
    const int lane = tid & 31;
    const int warp = tid >> 5;

    const int b = blockIdx.x / TILES;
    const int t = blockIdx.x % TILES;
    int px_base = t * NT;
    if (px_base > PIX - NT) px_base = PIX - NT;      // 3904, multiple of 64
    const int j0 = px_base >> 6;

    // ---------------- build A (Xh) in smem ----------------
    // fp32 staging [128 ch][128 px] overlays the W buffers (used before them)
    float* Xs = (float*)(smem + SM_W);
    for (int pass = 0; pass < 2; ++pass) {
        __syncthreads();
        if (pass == 0) {
            const float* src = xc + (size_t)b * 128 * PIX + px_base;
            for (int u = tid; u < 128 * 32; u += THREADS) {
                int row = u >> 5, c4 = (u & 31) << 2;
                *(float4*)&Xs[row * 128 + c4] =
                    *(const float4*)(src + (size_t)row * PIX + c4);
            }
        } else {
            const float* xr = x + (size_t)b * 64 * 64;
            for (int u = tid; u < 128 * 128; u += THREADS) {
                int row = u >> 7, col = u & 127;
                int c2 = row & 63, s = col >> 6, i = col & 63;
                Xs[row * 128 + col] = (row < 64)
                    ? xr[c2 * 64 + i]
                    : xr[c2 * 64 + ((i - (j0 + s + 1)) & 63)];
            }
        }
        __syncthreads();
        const int px = tid & 127;
        const int ch_lo = (tid >> 7) * 32;             // group of 32 channels
#pragma unroll
        for (int kk = 0; kk < 16; ++kk) {
            int c = ch_lo + 2 * kk;
            float a = Xs[c * 128 + px];
            float cg = Xs[(c + 1) * 128 + px];
            int chn = pass * 128 + c;
            uint32_t off = (uint32_t)(px * A_STRIDE + ((chn >> 3) << 4) + ((chn & 7) << 1));
            *(uint32_t*)(smem + SM_A + off) = pack_h2(a, cg);
        }
    }
    __syncthreads();

    // ---------------- warp tiling ----------------
    const int m0 = (warp & 1) * 64;
    const int n0 = (warp >> 1) * 32;

    const uint32_t a_lane = (uint32_t)((lane & 15) * A_STRIDE + ((lane >> 4) << 4));
    const uint32_t w_lane = (uint32_t)((lane & 15) * W_STRIDE + ((lane >> 4) << 4));
    const uint32_t a_base = sb + SM_A + (uint32_t)(m0 * A_STRIDE) + a_lane;

    const int qrow = lane >> 2;               // 0..7
    const int qcol = (lane & 3) * 2;          // 0,2,4,6

    float* ob = out + (size_t)b * 256 * PIX + px_base;

    // prefetch layer 0 chunk 0 into buf 0
    load_wchunk(sb + SM_W, g_Wh, g_Wl, 0, tid);

    for (int L = 0; L < 3; ++L) {
        float acc[4][4][4];
#pragma unroll
        for (int mt = 0; mt < 4; ++mt)
#pragma unroll
            for (int nt = 0; nt < 4; ++nt)
#pragma unroll
                for (int q = 0; q < 4; ++q) acc[mt][nt][q] = 0.f;

        const __half* WhL = g_Wh + (size_t)L * 65536;
        const __half* WlL = g_Wl + (size_t)L * 65536;

        for (int c = 0; c < NCHUNK; ++c) {
            CP_WAIT0();
            __syncthreads();      // chunk c visible; all warps past chunk c-1
            if (c + 1 < NCHUNK) {
                load_wchunk(sb + SM_W + (uint32_t)(((c + 1) & 1) * W_BUF),
                            WhL, WlL, c + 1, tid);
            } else if (L < 2) {
                // prefetch next layer's chunk 0 under this chunk + epilogue.
                // buf (NCHUNK)&1 == 0; its prior contents (chunk NCHUNK-2)
                // were fully consumed before this barrier.
                load_wchunk(sb + SM_W + (uint32_t)(((c + 1) & 1) * W_BUF),
                            g_Wh + (size_t)(L + 1) * 65536,
                            g_Wl + (size_t)(L + 1) * 65536, 0, tid);
            }

            const uint32_t wb = sb + SM_W + (uint32_t)((c & 1) * W_BUF);
            const uint32_t wh_base = wb + (uint32_t)(n0 * W_STRIDE) + w_lane;
            const uint32_t wl_base = wh_base + W_HALF;

#pragma unroll
            for (int ks = 0; ks < 4; ++ks) {
                const int kg = c * KCH + ks * 16;
                uint32_t afr[4][4], bh[2][4], bl[2][4];
#pragma unroll
                for (int mt = 0; mt < 4; ++mt)
                    ldsm4(afr[mt], a_base + (uint32_t)(mt * 16 * A_STRIDE + kg * 2));
#pragma unroll
                for (int n2 = 0; n2 < 2; ++n2) {
                    ldsm4(bh[n2], wh_base + (uint32_t)(n2 * 16 * W_STRIDE + ks * 32));
                    ldsm4(bl[n2], wl_base + (uint32_t)(n2 * 16 * W_STRIDE + ks * 32));
                }
                // 16 independent hi-MMAs ...
#pragma unroll
                for (int mt = 0; mt < 4; ++mt)
#pragma unroll
                    for (int nt = 0; nt < 4; ++nt) {
                        const int n2 = nt >> 1, h = nt & 1;
                        mma16816(acc[mt][nt], afr[mt], bh[n2][h], bh[n2][h + 2]);
                    }
                // ... then 16 independent lo-MMAs (acc reuse distance = 16)
#pragma unroll
                for (int mt = 0; mt < 4; ++mt)
#pragma unroll
                    for (int nt = 0; nt < 4; ++nt) {
                        const int n2 = nt >> 1, h = nt & 1;
                        mma16816(acc[mt][nt], afr[mt], bl[n2][h], bl[n2][h + 2]);
                    }
            }
        }

        __syncthreads();          // all reads of A done before rewrite

        const float* bl_ptr = (L == 0) ? b1 : (L == 1) ? b2 : b3;
        if (L < 2) {
#pragma unroll
            for (int mt = 0; mt < 4; ++mt) {
                const int pxr0 = m0 + mt * 16 + qrow;
#pragma unroll
                for (int nt = 0; nt < 4; ++nt) {
                    const int ch = n0 + nt * 8 + qcol;
                    const float bv0 = __ldg(bl_ptr + ch);
                    const float bv1 = __ldg(bl_ptr + ch + 1);
                    const uint32_t coff = (uint32_t)(((ch >> 3) << 4) + ((ch & 7) << 1));
#pragma unroll
                    for (int half = 0; half < 2; ++half) {
                        const int pxr = pxr0 + half * 8;
                        float v0 = fmaxf(acc[mt][nt][half * 2 + 0] + bv0, 0.f);
                        float v1 = fmaxf(acc[mt][nt][half * 2 + 1] + bv1, 0.f);
                        *(uint32_t*)(smem + SM_A + (uint32_t)(pxr * A_STRIDE) + coff) =
                            pack_h2(v0, v1);
                    }
                }
            }
            __syncthreads();      // new A visible before next layer
        } else {
#pragma unroll
            for (int mt = 0; mt < 4; ++mt) {
                const int pxr0 = m0 + mt * 16 + qrow;
#pragma unroll
                for (int nt = 0; nt < 4; ++nt) {
                    const int ch = n0 + nt * 8 + qcol;
                    const float bv0 = __ldg(bl_ptr + ch);
                    const float bv1 = __ldg(bl_ptr + ch + 1);
#pragma unroll
                    for (int half = 0; half < 2; ++half) {
                        const int pxr = pxr0 + half * 8;
                        ob[(size_t)ch * PIX + pxr] =
                            fmaxf(acc[mt][nt][half * 2 + 0] + bv0, 0.f);
                        ob[(size_t)(ch + 1) * PIX + pxr] =
                            fmaxf(acc[mt][nt][half * 2 + 1] + bv1, 0.f);
                    }
                }
            }
        }
    }
}

extern "C" void kernel_launch(void* const* d_in, const int* in_sizes, int n_in,
                              void* d_out, int out_size)
{
    (void)in_sizes; (void)n_in; (void)out_size;
    const float* x  = (const float*)d_in[0];
    const float* xc = (const float*)d_in[1];
    const float* W1 = (const float*)d_in[2];
    const float* b1 = (const float*)d_in[3];
    const float* W2 = (const float*)d_in[4];
    const float* b2 = (const float*)d_in[5];
    const float* W3 = (const float*)d_in[6];
    const float* b3 = (const float*)d_in[7];
    float* out = (float*)d_out;

    prep_split<<<256, 256>>>(W1, W2, W3);

    cudaFuncSetAttribute(pairs_mma_kernel,
                         cudaFuncAttributeMaxDynamicSharedMemorySize, SMEM_BYTES);
    pairs_mma_kernel<<<BATCH * TILES, THREADS, SMEM_BYTES>>>(
        x, xc, b1, b2, b3, out);
}